// round 11
// baseline (speedup 1.0000x reference)
#include <cuda_runtime.h>
#include <cuda_bf16.h>
#include <cstdint>

// ---------------- problem constants ----------------
#define BATCH  4096
#define DETERW 4096
#define HIDW   512
#define XW     2048            // 4*HID
#define OUTB   512
#define NBLK   8
#define GATES3 1536            // 3*OUTB
#define GATEW  12288           // 3*DETER
#define EPSV   1e-4f

// ---------------- scratch (device globals; no allocs allowed) ----------------
// 256B-aligned: cp.async-16 sources and float4/float2 accesses need >=16B base.
__device__ __align__(256) float g_actN[BATCH * 32];
__device__ __align__(256) float g_y[(size_t)BATCH * XW];        // branch GEMM raw
__device__ __align__(256) float g_X[(size_t)BATCH * XW];        // branch norm+silu
__device__ __align__(256) float g_h[(size_t)BATCH * DETERW];    // raw block-GEMM out
__device__ __align__(256) float g_nrm[(size_t)BATCH * DETERW];  // normed+silu
__device__ __align__(256) float g_gates[(size_t)BATCH * GATEW]; // gate GEMM raw

// ---------------- tile geometry ----------------
#define BM 128
#define BK 16
#define NST 4
#define AP 20    // A smem pitch: bank (20g+tg)%32 bijective -> conflict-free
#define A_STAGE (BM * AP)                 // 2560 floats

template <int BN_> struct Cfg;
template <> struct Cfg<256> { static const int BP = 264; };  // bank (8tg+8j+g)%32 bijective
template <> struct Cfg<128> { static const int BP = 136; };  // bank (8tg+g)%32 bijective

#define SMEM_B_256 (NST * (A_STAGE + BK * 264) * 4)   // 108544
#define SMEM_B_128 (NST * (A_STAGE + BK * 136) * 4)   // 75776

__device__ __forceinline__ uint32_t f2tf32(float x) {
    uint32_t r;
    asm("cvt.rna.tf32.f32 %0, %1;" : "=r"(r) : "f"(x));
    return r;
}

// ---------------- generic tf32 GEMM (templated tile width) ----------------
// C[:, coff + z*czs + n] = concat(A0[:, z*a0zs : +K0], A1)[M,K] @ W[z][K,N]
template <int BN_>
__global__ void __launch_bounds__(256)
gemm_tf32(const float* __restrict__ A0, int lda0, int K0, int a0zs,
          const float* __restrict__ A1, int lda1,
          const float* __restrict__ W, int ldw, long long wzs, int K,
          float* __restrict__ C, int ldc, int coff, int czs)
{
    constexpr int BP = Cfg<BN_>::BP;
    constexpr int B_STAGE = BK * BP;
    constexpr int JT = BN_ / 32;
    constexpr int WN = BN_ / 4;

    extern __shared__ float smem[];
    float* Asm = smem;
    float* Bsm = smem + NST * A_STAGE;

    const int tid = threadIdx.x;
    const int z  = blockIdx.z;
    const int n0 = blockIdx.x * BN_;
    const int m0 = blockIdx.y * BM;
    const float* Wz = W + (long long)z * wzs;
    const int a0c = z * a0zs;
    const long long ccol = (long long)coff + n0 + (long long)z * czs;

    const uint32_t sA = (uint32_t)__cvta_generic_to_shared(Asm);
    const uint32_t sB = (uint32_t)__cvta_generic_to_shared(Bsm);

    auto load_stage = [&](int st, int kt) {
        const int k0 = kt * BK;
        const float* Ab; int lda; int ac;
        if (k0 < K0) { Ab = A0; lda = lda0; ac = a0c + k0; }
        else         { Ab = A1; lda = lda1; ac = k0 - K0; }
        #pragma unroll
        for (int it = 0; it < 2; it++) {              // A: 128 rows x 16 floats
            int c = tid + it * 256;
            int row = c >> 2, cc = (c & 3) * 4;
            uint32_t dst = sA + (uint32_t)((st * A_STAGE + row * AP + cc) * 4);
            const float* src = Ab + (size_t)(m0 + row) * lda + ac + cc;
            asm volatile("cp.async.cg.shared.global.L2::128B [%0], [%1], 16;\n"
                         :: "r"(dst), "l"(src));
        }
        #pragma unroll
        for (int it = 0; it < BN_ / 64; it++) {       // B: 16 rows x BN_ floats
            int c = tid + it * 256;
            int row = c / (BN_ / 4), cc = (c % (BN_ / 4)) * 4;
            uint32_t dst = sB + (uint32_t)((st * B_STAGE + row * BP + cc) * 4);
            const float* src = Wz + (size_t)(k0 + row) * ldw + n0 + cc;
            asm volatile("cp.async.cg.shared.global.L2::128B [%0], [%1], 16;\n"
                         :: "r"(dst), "l"(src));
        }
        asm volatile("cp.async.commit_group;\n");
    };

    const int warp = tid >> 5, lane = tid & 31;
    const int g = lane >> 2, tg = lane & 3;
    const int wm = (warp >> 2) * 64;
    const int wn = (warp & 3) * WN;

    float acc[4][JT][4];
    #pragma unroll
    for (int i = 0; i < 4; i++)
        #pragma unroll
        for (int j = 0; j < JT; j++)
            #pragma unroll
            for (int k = 0; k < 4; k++) acc[i][j][k] = 0.f;

    const int nkt = K / BK;
    load_stage(0, 0);
    if (nkt > 1) load_stage(1, 1);
    if (nkt > 2) load_stage(2, 2);

    for (int kt = 0; kt < nkt; kt++) {
        if (kt + 3 < nkt) {
            load_stage((kt + 3) % NST, kt + 3);
            asm volatile("cp.async.wait_group 3;\n" ::: "memory");
        } else if (kt + 3 == nkt) {
            asm volatile("cp.async.wait_group 2;\n" ::: "memory");
        } else if (kt + 2 == nkt) {
            asm volatile("cp.async.wait_group 1;\n" ::: "memory");
        } else {
            asm volatile("cp.async.wait_group 0;\n" ::: "memory");
        }
        __syncthreads();
        const float* as = Asm + (kt % NST) * A_STAGE;
        const float* bs = Bsm + (kt % NST) * B_STAGE;
        #pragma unroll
        for (int s = 0; s < 2; s++) {
            uint32_t af[4][4], bf[JT][2];
            #pragma unroll
            for (int i = 0; i < 4; i++) {
                int r0 = wm + i * 16 + g;
                af[i][0] = f2tf32(as[r0 * AP + s * 8 + tg]);
                af[i][1] = f2tf32(as[(r0 + 8) * AP + s * 8 + tg]);
                af[i][2] = f2tf32(as[r0 * AP + s * 8 + tg + 4]);
                af[i][3] = f2tf32(as[(r0 + 8) * AP + s * 8 + tg + 4]);
            }
            #pragma unroll
            for (int j = 0; j < JT; j++) {
                int cn = wn + j * 8 + g;
                bf[j][0] = f2tf32(bs[(s * 8 + tg) * BP + cn]);
                bf[j][1] = f2tf32(bs[(s * 8 + tg + 4) * BP + cn]);
            }
            #pragma unroll
            for (int i = 0; i < 4; i++)
                #pragma unroll
                for (int j = 0; j < JT; j++) {
                    asm volatile(
                        "mma.sync.aligned.m16n8k8.row.col.f32.tf32.tf32.f32 "
                        "{%0,%1,%2,%3}, {%4,%5,%6,%7}, {%8,%9}, {%0,%1,%2,%3};"
                        : "+f"(acc[i][j][0]), "+f"(acc[i][j][1]),
                          "+f"(acc[i][j][2]), "+f"(acc[i][j][3])
                        : "r"(af[i][0]), "r"(af[i][1]), "r"(af[i][2]), "r"(af[i][3]),
                          "r"(bf[j][0]), "r"(bf[j][1]));
                }
        }
        __syncthreads();
    }

    // vectorized epilogue: column pairs (cn, cn+1) contiguous; cn even,
    // C 256B-aligned, ldc % 4 == 0 -> 8B-aligned float2 stores.
    #pragma unroll
    for (int i = 0; i < 4; i++) {
        int r0 = m0 + wm + i * 16 + g;
        #pragma unroll
        for (int j = 0; j < JT; j++) {
            long long cn = ccol + wn + j * 8 + tg * 2;
            *(float2*)&C[(size_t)r0 * ldc + cn]       = make_float2(acc[i][j][0], acc[i][j][1]);
            *(float2*)&C[(size_t)(r0 + 8) * ldc + cn] = make_float2(acc[i][j][2], acc[i][j][3]);
        }
    }
}

// ---------------- fused 4-branch GEMM (BN=128 body; z selects branch) ----------------
struct BrP { const float* A; int lda; int K; const float* W; int coff; };
struct Br4 { BrP b[4]; };

__global__ void __launch_bounds__(256)
gemm_br4(Br4 P, float* __restrict__ C)
{
    constexpr int BN_ = 128;
    constexpr int BP = Cfg<128>::BP;
    constexpr int B_STAGE = BK * BP;
    constexpr int JT = BN_ / 32;
    constexpr int WN = BN_ / 4;

    extern __shared__ float smem[];
    float* Asm = smem;
    float* Bsm = smem + NST * A_STAGE;

    const int tid = threadIdx.x;
    const BrP pb = P.b[blockIdx.z];
    const float* A = pb.A;
    const int lda = pb.lda;
    const int K   = pb.K;
    const float* W = pb.W;                 // [K, 512] row-major
    const int n0 = blockIdx.x * BN_;
    const int m0 = blockIdx.y * BM;
    const long long ccol = (long long)pb.coff + n0;

    const uint32_t sA = (uint32_t)__cvta_generic_to_shared(Asm);
    const uint32_t sB = (uint32_t)__cvta_generic_to_shared(Bsm);

    auto load_stage = [&](int st, int kt) {
        const int k0 = kt * BK;
        #pragma unroll
        for (int it = 0; it < 2; it++) {              // A: 128 rows x 16 floats
            int c = tid + it * 256;
            int row = c >> 2, cc = (c & 3) * 4;
            uint32_t dst = sA + (uint32_t)((st * A_STAGE + row * AP + cc) * 4);
            const float* src = A + (size_t)(m0 + row) * lda + k0 + cc;
            asm volatile("cp.async.cg.shared.global.L2::128B [%0], [%1], 16;\n"
                         :: "r"(dst), "l"(src));
        }
        #pragma unroll
        for (int it = 0; it < 2; it++) {              // B: 16 rows x 128 floats
            int c = tid + it * 256;
            int row = c >> 5, cc = (c & 31) * 4;
            uint32_t dst = sB + (uint32_t)((st * B_STAGE + row * BP + cc) * 4);
            const float* src = W + (size_t)(k0 + row) * HIDW + n0 + cc;
            asm volatile("cp.async.cg.shared.global.L2::128B [%0], [%1], 16;\n"
                         :: "r"(dst), "l"(src));
        }
        asm volatile("cp.async.commit_group;\n");
    };

    const int warp = tid >> 5, lane = tid & 31;
    const int g = lane >> 2, tg = lane & 3;
    const int wm = (warp >> 2) * 64;
    const int wn = (warp & 3) * WN;

    float acc[4][JT][4];
    #pragma unroll
    for (int i = 0; i < 4; i++)
        #pragma unroll
        for (int j = 0; j < JT; j++)
            #pragma unroll
            for (int k = 0; k < 4; k++) acc[i][j][k] = 0.f;

    const int nkt = K / BK;
    load_stage(0, 0);
    if (nkt > 1) load_stage(1, 1);
    if (nkt > 2) load_stage(2, 2);

    for (int kt = 0; kt < nkt; kt++) {
        if (kt + 3 < nkt) {
            load_stage((kt + 3) % NST, kt + 3);
            asm volatile("cp.async.wait_group 3;\n" ::: "memory");
        } else if (kt + 3 == nkt) {
            asm volatile("cp.async.wait_group 2;\n" ::: "memory");
        } else if (kt + 2 == nkt) {
            asm volatile("cp.async.wait_group 1;\n" ::: "memory");
        } else {
            asm volatile("cp.async.wait_group 0;\n" ::: "memory");
        }
        __syncthreads();
        const float* as = Asm + (kt % NST) * A_STAGE;
        const float* bs = Bsm + (kt % NST) * B_STAGE;
        #pragma unroll
        for (int s = 0; s < 2; s++) {
            uint32_t af[4][4], bf[JT][2];
            #pragma unroll
            for (int i = 0; i < 4; i++) {
                int r0 = wm + i * 16 + g;
                af[i][0] = f2tf32(as[r0 * AP + s * 8 + tg]);
                af[i][1] = f2tf32(as[(r0 + 8) * AP + s * 8 + tg]);
                af[i][2] = f2tf32(as[r0 * AP + s * 8 + tg + 4]);
                af[i][3] = f2tf32(as[(r0 + 8) * AP + s * 8 + tg + 4]);
            }
            #pragma unroll
            for (int j = 0; j < JT; j++) {
                int cn = wn + j * 8 + g;
                bf[j][0] = f2tf32(bs[(s * 8 + tg) * BP + cn]);
                bf[j][1] = f2tf32(bs[(s * 8 + tg + 4) * BP + cn]);
            }
            #pragma unroll
            for (int i = 0; i < 4; i++)
                #pragma unroll
                for (int j = 0; j < JT; j++) {
                    asm volatile(
                        "mma.sync.aligned.m16n8k8.row.col.f32.tf32.tf32.f32 "
                        "{%0,%1,%2,%3}, {%4,%5,%6,%7}, {%8,%9}, {%0,%1,%2,%3};"
                        : "+f"(acc[i][j][0]), "+f"(acc[i][j][1]),
                          "+f"(acc[i][j][2]), "+f"(acc[i][j][3])
                        : "r"(af[i][0]), "r"(af[i][1]), "r"(af[i][2]), "r"(af[i][3]),
                          "r"(bf[j][0]), "r"(bf[j][1]));
                }
        }
        __syncthreads();
    }

    #pragma unroll
    for (int i = 0; i < 4; i++) {
        int r0 = m0 + wm + i * 16 + g;
        #pragma unroll
        for (int j = 0; j < JT; j++) {
            long long cn = ccol + wn + j * 8 + tg * 2;
            *(float2*)&C[(size_t)r0 * XW + cn]       = make_float2(acc[i][j][0], acc[i][j][1]);
            *(float2*)&C[(size_t)(r0 + 8) * XW + cn] = make_float2(acc[i][j][2], acc[i][j][3]);
        }
    }
}

// ---------------- elementwise kernels ----------------
__global__ void actnorm_k(const float* __restrict__ a, float* __restrict__ o, int n) {
    int i = blockIdx.x * blockDim.x + threadIdx.x;
    if (i < n) { float v = a[i]; o[i] = v / fmaxf(fabsf(v), 1.0f); }
}

__device__ __forceinline__ float siluf(float u) { return u / (1.0f + expf(-u)); }

// per-branch RMSNorm(512) + bias + SiLU:  y[B,2048] -> X[B,2048]
// 128 threads; one float4 per thread (128*4 = 512 elements).
// Alignment: g_y/g_X 256B-aligned; row offset 8KB mult; branch offset 2KB mult.
__global__ void norm_silu_512(const float* __restrict__ y,
                              const float* b0, const float* g0,
                              const float* b1, const float* g1,
                              const float* b2, const float* g2,
                              const float* b3, const float* g3,
                              float* __restrict__ X)
{
    int row = blockIdx.x, br = blockIdx.y, t = threadIdx.x;  // 128 threads
    const float* bias; const float* gain;
    if      (br == 0) { bias = b0; gain = g0; }
    else if (br == 1) { bias = b1; gain = g1; }
    else if (br == 2) { bias = b2; gain = g2; }
    else              { bias = b3; gain = g3; }
    const float4* src = (const float4*)(y + (size_t)row * XW + br * HIDW);
    float4 v = src[t];
    float4 b4 = ((const float4*)bias)[t];
    v.x += b4.x; v.y += b4.y; v.z += b4.z; v.w += b4.w;
    float ss = v.x * v.x + v.y * v.y + v.z * v.z + v.w * v.w;
    #pragma unroll
    for (int o = 16; o; o >>= 1) ss += __shfl_xor_sync(0xFFFFFFFFu, ss, o);
    __shared__ float sred[4];
    if ((t & 31) == 0) sred[t >> 5] = ss;
    __syncthreads();
    ss = sred[0] + sred[1] + sred[2] + sred[3];
    float rs = rsqrtf(ss * (1.0f / 512.0f) + EPSV);
    float4 g4 = ((const float4*)gain)[t];
    float4 r;
    r.x = siluf(v.x * rs * g4.x);
    r.y = siluf(v.y * rs * g4.y);
    r.z = siluf(v.z * rs * g4.z);
    r.w = siluf(v.w * rs * g4.w);
    ((float4*)(X + (size_t)row * XW + br * HIDW))[t] = r;
}

// full-width RMSNorm(4096) + bias + SiLU
__global__ void norm_silu_4096(const float* __restrict__ in,
                               const float* __restrict__ bias,
                               const float* __restrict__ gain,
                               float* __restrict__ out)
{
    int row = blockIdx.x, t = threadIdx.x;  // 256 threads
    const float4* src = (const float4*)(in + (size_t)row * DETERW);
    const float4* bs  = (const float4*)bias;
    const float4* gs  = (const float4*)gain;
    float4 v[4]; float ss = 0.f;
    #pragma unroll
    for (int k = 0; k < 4; k++) {
        int c = t + k * 256;
        float4 x = src[c], b = bs[c];
        x.x += b.x; x.y += b.y; x.z += b.z; x.w += b.w;
        ss += x.x * x.x + x.y * x.y + x.z * x.z + x.w * x.w;
        v[k] = x;
    }
    #pragma unroll
    for (int o = 16; o; o >>= 1) ss += __shfl_xor_sync(0xFFFFFFFFu, ss, o);
    __shared__ float sred[8];
    if ((t & 31) == 0) sred[t >> 5] = ss;
    __syncthreads();
    ss = 0.f;
    #pragma unroll
    for (int w = 0; w < 8; w++) ss += sred[w];
    float rs = rsqrtf(ss * (1.0f / 4096.0f) + EPSV);
    float4* dst = (float4*)(out + (size_t)row * DETERW);
    #pragma unroll
    for (int k = 0; k < 4; k++) {
        int c = t + k * 256;
        float4 x = v[k], gg = gs[c], r;
        r.x = siluf(x.x * rs * gg.x);
        r.y = siluf(x.y * rs * gg.y);
        r.z = siluf(x.z * rs * gg.z);
        r.w = siluf(x.w * rs * gg.w);
        dst[c] = r;
    }
}

// GRU gate nonlinearity + state blend
__global__ void gru_k(const float* __restrict__ gates, const float* __restrict__ bg,
                      const float* __restrict__ deter, float* __restrict__ out)
{
    int i = blockIdx.x * 256 + threadIdx.x;         // i = b*4096 + d
    int d = i & 4095;
    size_t b = (size_t)(i >> 12);
    int gblk = d >> 9, ii = d & 511;
    size_t base = b * GATEW + (size_t)gblk * GATES3 + ii;
    int bb = gblk * GATES3 + ii;
    float r = gates[base]        + bg[bb];
    float c = gates[base + 512]  + bg[bb + 512];
    float u = gates[base + 1024] + bg[bb + 1024];
    r = 1.0f / (1.0f + expf(-r));
    c = tanhf(r * c);
    u = 1.0f / (1.0f + expf(-(u - 1.0f)));
    out[i] = u * c + (1.0f - u) * deter[i];
}

// ---------------- launch ----------------
extern "C" void kernel_launch(void* const* d_in, const int* in_sizes, int n_in,
                              void* d_out, int out_size)
{
    const float* stoch  = (const float*)d_in[0];
    const float* deter  = (const float*)d_in[1];
    const float* action = (const float*)d_in[2];
    const float* demb   = (const float*)d_in[3];
    const float* W0 = (const float*)d_in[4];  const float* b0 = (const float*)d_in[5];  const float* gg0 = (const float*)d_in[6];
    const float* W1 = (const float*)d_in[7];  const float* b1 = (const float*)d_in[8];  const float* gg1 = (const float*)d_in[9];
    const float* W2 = (const float*)d_in[10]; const float* b2 = (const float*)d_in[11]; const float* gg2 = (const float*)d_in[12];
    const float* W3 = (const float*)d_in[13]; const float* b3 = (const float*)d_in[14]; const float* gg3 = (const float*)d_in[15];
    const float* Wh0 = (const float*)d_in[16]; const float* bh0 = (const float*)d_in[17]; const float* gh0 = (const float*)d_in[18];
    const float* Wh1 = (const float*)d_in[19]; const float* bh1 = (const float*)d_in[20]; const float* gh1 = (const float*)d_in[21];
    const float* Wg  = (const float*)d_in[22]; const float* bg  = (const float*)d_in[23];
    float* out = (float*)d_out;

    float *actN, *y, *X, *h, *nrm, *gates;
    cudaGetSymbolAddress((void**)&actN,  g_actN);
    cudaGetSymbolAddress((void**)&y,     g_y);
    cudaGetSymbolAddress((void**)&X,     g_X);
    cudaGetSymbolAddress((void**)&h,     g_h);
    cudaGetSymbolAddress((void**)&nrm,   g_nrm);
    cudaGetSymbolAddress((void**)&gates, g_gates);

    // allow > 48KB dynamic smem (idempotent; host-side, graph-capture safe)
    cudaFuncSetAttribute(gemm_tf32<256>, cudaFuncAttributeMaxDynamicSharedMemorySize,
                         SMEM_B_256);
    cudaFuncSetAttribute(gemm_br4, cudaFuncAttributeMaxDynamicSharedMemorySize,
                         SMEM_B_128);

    // 1. action / clip(|action|, 1)
    actnorm_k<<<(BATCH * 32 + 255) / 256, 256>>>(action, actN, BATCH * 32);

    // 2. all four branch GEMMs in ONE launch (z = branch), 512 CTAs
    Br4 P;
    P.b[0] = { deter, 4096, 4096, W0, 0    };
    P.b[1] = { stoch, 1024, 1024, W1, 512  };
    P.b[2] = { actN,  32,   32,   W2, 1024 };
    P.b[3] = { demb,  16,   16,   W3, 1536 };
    gemm_br4<<<dim3(4, 32, 4), 256, SMEM_B_128>>>(P, y);

    // 3. per-branch RMSNorm + SiLU -> X
    norm_silu_512<<<dim3(BATCH, 4), 128>>>(y, b0, gg0, b1, gg1, b2, gg2, b3, gg3, X);

    // 4. hidden block 0: concat(deter_g, X) [K=2560] @ Wh0[g] -> h  (512 CTAs)
    gemm_tf32<256><<<dim3(2, 32, 8), 256, SMEM_B_256>>>(deter, 4096, 512, 512, X, XW,
                                       Wh0, 512, (long long)2560 * 512, 2560,
                                       h, DETERW, 0, 512);
    norm_silu_4096<<<BATCH, 256>>>(h, bh0, gh0, nrm);

    // 5. hidden block 1  (512 CTAs)
    gemm_tf32<256><<<dim3(2, 32, 8), 256, SMEM_B_256>>>(nrm, 4096, 512, 512, nrm, 4096,
                                       Wh1, 512, (long long)512 * 512, 512,
                                       h, DETERW, 0, 512);
    norm_silu_4096<<<BATCH, 256>>>(h, bh1, gh1, nrm);

    // 6. GRU gate GEMM: [B,8,512] @ Wg[g][512,1536] -> gates  (1536 CTAs)
    gemm_tf32<256><<<dim3(6, 32, 8), 256, SMEM_B_256>>>(nrm, 4096, 512, 512, nrm, 4096,
                                        Wg, 1536, (long long)512 * 1536, 512,
                                        gates, GATEW, 0, 1536);

    // 7. GRU nonlinearity + blend with deter
    gru_k<<<(BATCH * DETERW) / 256, 256>>>(gates, bg, deter, out);
}

// round 17
// speedup vs baseline: 1.0694x; 1.0694x over previous
#include <cuda_runtime.h>
#include <cuda_bf16.h>
#include <cstdint>

// ---------------- problem constants ----------------
#define BATCH  4096
#define DETERW 4096
#define HIDW   512
#define XW     2048            // 4*HID
#define OUTB   512
#define NBLK   8
#define GATES3 1536            // 3*OUTB
#define GATEW  12288           // 3*DETER
#define EPSV   1e-4f

// ---------------- scratch (device globals; no allocs allowed) ----------------
__device__ __align__(256) float g_actN[BATCH * 32];
__device__ __align__(256) float g_y[(size_t)BATCH * XW];
__device__ __align__(256) float g_X[(size_t)BATCH * XW];
__device__ __align__(256) float g_h[(size_t)BATCH * DETERW];
__device__ __align__(256) float g_nrm[(size_t)BATCH * DETERW];
__device__ __align__(256) float g_gates[(size_t)BATCH * GATEW];

// ---------------- tile geometry: BN=128, 2 CTAs/SM ----------------
#define BM 128
#define BN 128
#define BK 16
#define NST 4
#define AP 20    // A smem pitch: bank (20g+tg)%32 bijective -> conflict-free
#define BP 136   // B smem pitch: bank (8tg+g)%32 bijective -> conflict-free
#define A_STAGE (BM * AP)                 // 2560 floats
#define B_STAGE (BK * BP)                 // 2176 floats
#define JT 4                              // per-warp n8 tiles (BN/32)
#define WN 32                             // per-warp n extent (BN/4)
#define SMEM_B (NST * (A_STAGE + B_STAGE) * 4)   // 75776 B; x2 CTAs = 151552 < 228KB

__device__ __forceinline__ uint32_t f2tf32(float x) {
    uint32_t r;
    asm("cvt.rna.tf32.f32 %0, %1;" : "=r"(r) : "f"(x));
    return r;
}

// ---------------- generic tf32 GEMM ----------------
// C[:, coff + z*czs + n] = concat(A0[:, z*a0zs : +K0], A1)[M,K] @ W[z][K,N]
__global__ void __launch_bounds__(256, 2)
gemm_tf32(const float* __restrict__ A0, int lda0, int K0, int a0zs,
          const float* __restrict__ A1, int lda1,
          const float* __restrict__ W, int ldw, long long wzs, int K,
          float* __restrict__ C, int ldc, int coff, int czs)
{
    extern __shared__ float smem[];
    float* Asm = smem;
    float* Bsm = smem + NST * A_STAGE;

    const int tid = threadIdx.x;
    const int z  = blockIdx.z;
    const int n0 = blockIdx.x * BN;
    const int m0 = blockIdx.y * BM;
    const float* Wz = W + (long long)z * wzs;
    const int a0c = z * a0zs;
    const long long ccol = (long long)coff + n0 + (long long)z * czs;

    const uint32_t sA = (uint32_t)__cvta_generic_to_shared(Asm);
    const uint32_t sB = (uint32_t)__cvta_generic_to_shared(Bsm);

    auto load_stage = [&](int st, int kt) {
        const int k0 = kt * BK;
        const float* Ab; int lda; int ac;
        if (k0 < K0) { Ab = A0; lda = lda0; ac = a0c + k0; }
        else         { Ab = A1; lda = lda1; ac = k0 - K0; }
        #pragma unroll
        for (int it = 0; it < 2; it++) {              // A: 128 rows x 16 floats
            int c = tid + it * 256;
            int row = c >> 2, cc = (c & 3) * 4;
            uint32_t dst = sA + (uint32_t)((st * A_STAGE + row * AP + cc) * 4);
            const float* src = Ab + (size_t)(m0 + row) * lda + ac + cc;
            asm volatile("cp.async.cg.shared.global.L2::128B [%0], [%1], 16;\n"
                         :: "r"(dst), "l"(src));
        }
        #pragma unroll
        for (int it = 0; it < 2; it++) {              // B: 16 rows x 128 floats
            int c = tid + it * 256;
            int row = c >> 5, cc = (c & 31) * 4;
            uint32_t dst = sB + (uint32_t)((st * B_STAGE + row * BP + cc) * 4);
            const float* src = Wz + (size_t)(k0 + row) * ldw + n0 + cc;
            asm volatile("cp.async.cg.shared.global.L2::128B [%0], [%1], 16;\n"
                         :: "r"(dst), "l"(src));
        }
        asm volatile("cp.async.commit_group;\n");
    };

    const int warp = tid >> 5, lane = tid & 31;
    const int g = lane >> 2, tg = lane & 3;
    const int wm = (warp >> 2) * 64;
    const int wn = (warp & 3) * WN;

    float acc[4][JT][4];
    #pragma unroll
    for (int i = 0; i < 4; i++)
        #pragma unroll
        for (int j = 0; j < JT; j++)
            #pragma unroll
            for (int k = 0; k < 4; k++) acc[i][j][k] = 0.f;

    const int nkt = K / BK;
    load_stage(0, 0);
    if (nkt > 1) load_stage(1, 1);
    if (nkt > 2) load_stage(2, 2);

    for (int kt = 0; kt < nkt; kt++) {
        // wait until stage kt's group completed (2/1/0 newer groups allowed)
        if (kt + 2 < nkt) {
            asm volatile("cp.async.wait_group 2;\n" ::: "memory");
        } else if (kt + 1 < nkt) {
            asm volatile("cp.async.wait_group 1;\n" ::: "memory");
        } else {
            asm volatile("cp.async.wait_group 0;\n" ::: "memory");
        }
        // single barrier: publishes stage kt AND proves all warps finished
        // reading stage kt-1 == (kt+3)%NST, so the next load below is safe.
        __syncthreads();
        if (kt + 3 < nkt) load_stage((kt + 3) % NST, kt + 3);

        const float* as = Asm + (kt % NST) * A_STAGE;
        const float* bs = Bsm + (kt % NST) * B_STAGE;
        #pragma unroll
        for (int s = 0; s < 2; s++) {
            uint32_t af[4][4], bf[JT][2];
            #pragma unroll
            for (int i = 0; i < 4; i++) {
                int r0 = wm + i * 16 + g;
                af[i][0] = f2tf32(as[r0 * AP + s * 8 + tg]);
                af[i][1] = f2tf32(as[(r0 + 8) * AP + s * 8 + tg]);
                af[i][2] = f2tf32(as[r0 * AP + s * 8 + tg + 4]);
                af[i][3] = f2tf32(as[(r0 + 8) * AP + s * 8 + tg + 4]);
            }
            #pragma unroll
            for (int j = 0; j < JT; j++) {
                int cn = wn + j * 8 + g;
                bf[j][0] = f2tf32(bs[(s * 8 + tg) * BP + cn]);
                bf[j][1] = f2tf32(bs[(s * 8 + tg + 4) * BP + cn]);
            }
            #pragma unroll
            for (int i = 0; i < 4; i++)
                #pragma unroll
                for (int j = 0; j < JT; j++) {
                    asm volatile(
                        "mma.sync.aligned.m16n8k8.row.col.f32.tf32.tf32.f32 "
                        "{%0,%1,%2,%3}, {%4,%5,%6,%7}, {%8,%9}, {%0,%1,%2,%3};"
                        : "+f"(acc[i][j][0]), "+f"(acc[i][j][1]),
                          "+f"(acc[i][j][2]), "+f"(acc[i][j][3])
                        : "r"(af[i][0]), "r"(af[i][1]), "r"(af[i][2]), "r"(af[i][3]),
                          "r"(bf[j][0]), "r"(bf[j][1]));
                }
        }
    }

    #pragma unroll
    for (int i = 0; i < 4; i++) {
        int r0 = m0 + wm + i * 16 + g;
        #pragma unroll
        for (int j = 0; j < JT; j++) {
            long long cn = ccol + wn + j * 8 + tg * 2;
            *(float2*)&C[(size_t)r0 * ldc + cn]       = make_float2(acc[i][j][0], acc[i][j][1]);
            *(float2*)&C[(size_t)(r0 + 8) * ldc + cn] = make_float2(acc[i][j][2], acc[i][j][3]);
        }
    }
}

// ---------------- fused 4-branch GEMM (same body; z selects branch) ----------------
struct BrP { const float* A; int lda; int K; const float* W; int coff; };
struct Br4 { BrP b[4]; };

__global__ void __launch_bounds__(256, 2)
gemm_br4(Br4 P, float* __restrict__ C)
{
    extern __shared__ float smem[];
    float* Asm = smem;
    float* Bsm = smem + NST * A_STAGE;

    const int tid = threadIdx.x;
    const BrP pb = P.b[blockIdx.z];
    const float* A = pb.A;
    const int lda = pb.lda;
    const int K   = pb.K;
    const float* W = pb.W;                 // [K, 512] row-major
    const int n0 = blockIdx.x * BN;
    const int m0 = blockIdx.y * BM;
    const long long ccol = (long long)pb.coff + n0;

    const uint32_t sA = (uint32_t)__cvta_generic_to_shared(Asm);
    const uint32_t sB = (uint32_t)__cvta_generic_to_shared(Bsm);

    auto load_stage = [&](int st, int kt) {
        const int k0 = kt * BK;
        #pragma unroll
        for (int it = 0; it < 2; it++) {
            int c = tid + it * 256;
            int row = c >> 2, cc = (c & 3) * 4;
            uint32_t dst = sA + (uint32_t)((st * A_STAGE + row * AP + cc) * 4);
            const float* src = A + (size_t)(m0 + row) * lda + k0 + cc;
            asm volatile("cp.async.cg.shared.global.L2::128B [%0], [%1], 16;\n"
                         :: "r"(dst), "l"(src));
        }
        #pragma unroll
        for (int it = 0; it < 2; it++) {
            int c = tid + it * 256;
            int row = c >> 5, cc = (c & 31) * 4;
            uint32_t dst = sB + (uint32_t)((st * B_STAGE + row * BP + cc) * 4);
            const float* src = W + (size_t)(k0 + row) * HIDW + n0 + cc;
            asm volatile("cp.async.cg.shared.global.L2::128B [%0], [%1], 16;\n"
                         :: "r"(dst), "l"(src));
        }
        asm volatile("cp.async.commit_group;\n");
    };

    const int warp = tid >> 5, lane = tid & 31;
    const int g = lane >> 2, tg = lane & 3;
    const int wm = (warp >> 2) * 64;
    const int wn = (warp & 3) * WN;

    float acc[4][JT][4];
    #pragma unroll
    for (int i = 0; i < 4; i++)
        #pragma unroll
        for (int j = 0; j < JT; j++)
            #pragma unroll
            for (int k = 0; k < 4; k++) acc[i][j][k] = 0.f;

    const int nkt = K / BK;
    load_stage(0, 0);
    if (nkt > 1) load_stage(1, 1);
    if (nkt > 2) load_stage(2, 2);

    for (int kt = 0; kt < nkt; kt++) {
        if (kt + 2 < nkt) {
            asm volatile("cp.async.wait_group 2;\n" ::: "memory");
        } else if (kt + 1 < nkt) {
            asm volatile("cp.async.wait_group 1;\n" ::: "memory");
        } else {
            asm volatile("cp.async.wait_group 0;\n" ::: "memory");
        }
        __syncthreads();
        if (kt + 3 < nkt) load_stage((kt + 3) % NST, kt + 3);

        const float* as = Asm + (kt % NST) * A_STAGE;
        const float* bs = Bsm + (kt % NST) * B_STAGE;
        #pragma unroll
        for (int s = 0; s < 2; s++) {
            uint32_t af[4][4], bf[JT][2];
            #pragma unroll
            for (int i = 0; i < 4; i++) {
                int r0 = wm + i * 16 + g;
                af[i][0] = f2tf32(as[r0 * AP + s * 8 + tg]);
                af[i][1] = f2tf32(as[(r0 + 8) * AP + s * 8 + tg]);
                af[i][2] = f2tf32(as[r0 * AP + s * 8 + tg + 4]);
                af[i][3] = f2tf32(as[(r0 + 8) * AP + s * 8 + tg + 4]);
            }
            #pragma unroll
            for (int j = 0; j < JT; j++) {
                int cn = wn + j * 8 + g;
                bf[j][0] = f2tf32(bs[(s * 8 + tg) * BP + cn]);
                bf[j][1] = f2tf32(bs[(s * 8 + tg + 4) * BP + cn]);
            }
            #pragma unroll
            for (int i = 0; i < 4; i++)
                #pragma unroll
                for (int j = 0; j < JT; j++) {
                    asm volatile(
                        "mma.sync.aligned.m16n8k8.row.col.f32.tf32.tf32.f32 "
                        "{%0,%1,%2,%3}, {%4,%5,%6,%7}, {%8,%9}, {%0,%1,%2,%3};"
                        : "+f"(acc[i][j][0]), "+f"(acc[i][j][1]),
                          "+f"(acc[i][j][2]), "+f"(acc[i][j][3])
                        : "r"(af[i][0]), "r"(af[i][1]), "r"(af[i][2]), "r"(af[i][3]),
                          "r"(bf[j][0]), "r"(bf[j][1]));
                }
        }
    }

    #pragma unroll
    for (int i = 0; i < 4; i++) {
        int r0 = m0 + wm + i * 16 + g;
        #pragma unroll
        for (int j = 0; j < JT; j++) {
            long long cn = ccol + wn + j * 8 + tg * 2;
            *(float2*)&C[(size_t)r0 * XW + cn]       = make_float2(acc[i][j][0], acc[i][j][1]);
            *(float2*)&C[(size_t)(r0 + 8) * XW + cn] = make_float2(acc[i][j][2], acc[i][j][3]);
        }
    }
}

// ---------------- elementwise kernels ----------------
__global__ void actnorm_k(const float* __restrict__ a, float* __restrict__ o, int n) {
    int i = blockIdx.x * blockDim.x + threadIdx.x;
    if (i < n) { float v = a[i]; o[i] = v / fmaxf(fabsf(v), 1.0f); }
}

__device__ __forceinline__ float siluf(float u) { return u / (1.0f + expf(-u)); }

// per-branch RMSNorm(512) + bias + SiLU; one float4 per thread
__global__ void norm_silu_512(const float* __restrict__ y,
                              const float* b0, const float* g0,
                              const float* b1, const float* g1,
                              const float* b2, const float* g2,
                              const float* b3, const float* g3,
                              float* __restrict__ X)
{
    int row = blockIdx.x, br = blockIdx.y, t = threadIdx.x;  // 128 threads
    const float* bias; const float* gain;
    if      (br == 0) { bias = b0; gain = g0; }
    else if (br == 1) { bias = b1; gain = g1; }
    else if (br == 2) { bias = b2; gain = g2; }
    else              { bias = b3; gain = g3; }
    const float4* src = (const float4*)(y + (size_t)row * XW + br * HIDW);
    float4 v = src[t];
    float4 b4 = ((const float4*)bias)[t];
    v.x += b4.x; v.y += b4.y; v.z += b4.z; v.w += b4.w;
    float ss = v.x * v.x + v.y * v.y + v.z * v.z + v.w * v.w;
    #pragma unroll
    for (int o = 16; o; o >>= 1) ss += __shfl_xor_sync(0xFFFFFFFFu, ss, o);
    __shared__ float sred[4];
    if ((t & 31) == 0) sred[t >> 5] = ss;
    __syncthreads();
    ss = sred[0] + sred[1] + sred[2] + sred[3];
    float rs = rsqrtf(ss * (1.0f / 512.0f) + EPSV);
    float4 g4 = ((const float4*)gain)[t];
    float4 r;
    r.x = siluf(v.x * rs * g4.x);
    r.y = siluf(v.y * rs * g4.y);
    r.z = siluf(v.z * rs * g4.z);
    r.w = siluf(v.w * rs * g4.w);
    ((float4*)(X + (size_t)row * XW + br * HIDW))[t] = r;
}

// full-width RMSNorm(4096) + bias + SiLU
__global__ void norm_silu_4096(const float* __restrict__ in,
                               const float* __restrict__ bias,
                               const float* __restrict__ gain,
                               float* __restrict__ out)
{
    int row = blockIdx.x, t = threadIdx.x;  // 256 threads
    const float4* src = (const float4*)(in + (size_t)row * DETERW);
    const float4* bs  = (const float4*)bias;
    const float4* gs  = (const float4*)gain;
    float4 v[4]; float ss = 0.f;
    #pragma unroll
    for (int k = 0; k < 4; k++) {
        int c = t + k * 256;
        float4 x = src[c], b = bs[c];
        x.x += b.x; x.y += b.y; x.z += b.z; x.w += b.w;
        ss += x.x * x.x + x.y * x.y + x.z * x.z + x.w * x.w;
        v[k] = x;
    }
    #pragma unroll
    for (int o = 16; o; o >>= 1) ss += __shfl_xor_sync(0xFFFFFFFFu, ss, o);
    __shared__ float sred[8];
    if ((t & 31) == 0) sred[t >> 5] = ss;
    __syncthreads();
    ss = 0.f;
    #pragma unroll
    for (int w = 0; w < 8; w++) ss += sred[w];
    float rs = rsqrtf(ss * (1.0f / 4096.0f) + EPSV);
    float4* dst = (float4*)(out + (size_t)row * DETERW);
    #pragma unroll
    for (int k = 0; k < 4; k++) {
        int c = t + k * 256;
        float4 x = v[k], gg = gs[c], r;
        r.x = siluf(x.x * rs * gg.x);
        r.y = siluf(x.y * rs * gg.y);
        r.z = siluf(x.z * rs * gg.z);
        r.w = siluf(x.w * rs * gg.w);
        dst[c] = r;
    }
}

// GRU gate nonlinearity + state blend
__global__ void gru_k(const float* __restrict__ gates, const float* __restrict__ bg,
                      const float* __restrict__ deter, float* __restrict__ out)
{
    int i = blockIdx.x * 256 + threadIdx.x;         // i = b*4096 + d
    int d = i & 4095;
    size_t b = (size_t)(i >> 12);
    int gblk = d >> 9, ii = d & 511;
    size_t base = b * GATEW + (size_t)gblk * GATES3 + ii;
    int bb = gblk * GATES3 + ii;
    float r = gates[base]        + bg[bb];
    float c = gates[base + 512]  + bg[bb + 512];
    float u = gates[base + 1024] + bg[bb + 1024];
    r = 1.0f / (1.0f + expf(-r));
    c = tanhf(r * c);
    u = 1.0f / (1.0f + expf(-(u - 1.0f)));
    out[i] = u * c + (1.0f - u) * deter[i];
}

// ---------------- launch ----------------
extern "C" void kernel_launch(void* const* d_in, const int* in_sizes, int n_in,
                              void* d_out, int out_size)
{
    const float* stoch  = (const float*)d_in[0];
    const float* deter  = (const float*)d_in[1];
    const float* action = (const float*)d_in[2];
    const float* demb   = (const float*)d_in[3];
    const float* W0 = (const float*)d_in[4];  const float* b0 = (const float*)d_in[5];  const float* gg0 = (const float*)d_in[6];
    const float* W1 = (const float*)d_in[7];  const float* b1 = (const float*)d_in[8];  const float* gg1 = (const float*)d_in[9];
    const float* W2 = (const float*)d_in[10]; const float* b2 = (const float*)d_in[11]; const float* gg2 = (const float*)d_in[12];
    const float* W3 = (const float*)d_in[13]; const float* b3 = (const float*)d_in[14]; const float* gg3 = (const float*)d_in[15];
    const float* Wh0 = (const float*)d_in[16]; const float* bh0 = (const float*)d_in[17]; const float* gh0 = (const float*)d_in[18];
    const float* Wh1 = (const float*)d_in[19]; const float* bh1 = (const float*)d_in[20]; const float* gh1 = (const float*)d_in[21];
    const float* Wg  = (const float*)d_in[22]; const float* bg  = (const float*)d_in[23];
    float* out = (float*)d_out;

    float *actN, *y, *X, *h, *nrm, *gates;
    cudaGetSymbolAddress((void**)&actN,  g_actN);
    cudaGetSymbolAddress((void**)&y,     g_y);
    cudaGetSymbolAddress((void**)&X,     g_X);
    cudaGetSymbolAddress((void**)&h,     g_h);
    cudaGetSymbolAddress((void**)&nrm,   g_nrm);
    cudaGetSymbolAddress((void**)&gates, g_gates);

    cudaFuncSetAttribute(gemm_tf32, cudaFuncAttributeMaxDynamicSharedMemorySize,
                         SMEM_B);
    cudaFuncSetAttribute(gemm_br4, cudaFuncAttributeMaxDynamicSharedMemorySize,
                         SMEM_B);

    // 1. action / clip(|action|, 1)
    actnorm_k<<<(BATCH * 32 + 255) / 256, 256>>>(action, actN, BATCH * 32);

    // 2. all four branch GEMMs in ONE launch (z = branch), 512 CTAs
    Br4 P;
    P.b[0] = { deter, 4096, 4096, W0, 0    };
    P.b[1] = { stoch, 1024, 1024, W1, 512  };
    P.b[2] = { actN,  32,   32,   W2, 1024 };
    P.b[3] = { demb,  16,   16,   W3, 1536 };
    gemm_br4<<<dim3(4, 32, 4), 256, SMEM_B>>>(P, y);

    // 3. per-branch RMSNorm + SiLU -> X
    norm_silu_512<<<dim3(BATCH, 4), 128>>>(y, b0, gg0, b1, gg1, b2, gg2, b3, gg3, X);

    // 4. hidden block 0: concat(deter_g, X) [K=2560] @ Wh0[g] -> h  (1024 CTAs)
    gemm_tf32<<<dim3(4, 32, 8), 256, SMEM_B>>>(deter, 4096, 512, 512, X, XW,
                                       Wh0, 512, (long long)2560 * 512, 2560,
                                       h, DETERW, 0, 512);
    norm_silu_4096<<<BATCH, 256>>>(h, bh0, gh0, nrm);

    // 5. hidden block 1  (1024 CTAs)
    gemm_tf32<<<dim3(4, 32, 8), 256, SMEM_B>>>(nrm, 4096, 512, 512, nrm, 4096,
                                       Wh1, 512, (long long)512 * 512, 512,
                                       h, DETERW, 0, 512);
    norm_silu_4096<<<BATCH, 256>>>(h, bh1, gh1, nrm);

    // 6. GRU gate GEMM  (3072 CTAs)
    gemm_tf32<<<dim3(12, 32, 8), 256, SMEM_B>>>(nrm, 4096, 512, 512, nrm, 4096,
                                        Wg, 1536, (long long)512 * 1536, 512,
                                        gates, GATEW, 0, 1536);

    // 7. GRU nonlinearity + blend with deter
    gru_k<<<(BATCH * DETERW) / 256, 256>>>(gates, bg, deter, out);
}